// round 3
// baseline (speedup 1.0000x reference)
#include <cuda_runtime.h>
#include <math.h>

#define T_TOK 2048
#define H_DIM 512
#define I_DIM 512
#define E_NUM 8
#define KTOP  4

// ---------------- scratch (device globals, no allocs) ----------------
__device__ float g_t[T_TOK * H_DIM];                 // RMSNorm output
__device__ float g_a[(size_t)E_NUM * T_TOK * I_DIM]; // SwiGLU activations per expert slot
__device__ int   g_cnt[E_NUM];                       // tokens routed to each expert
__device__ int   g_tok[E_NUM * T_TOK];               // gathered token ids
__device__ float g_cw [E_NUM * T_TOK];               // combine coefficient per slot
__device__ float g_sumP[E_NUM];                      // sum of gate probs
__device__ float g_imp [E_NUM];                      // sum of gate logits (importance)
__device__ float g_wc  [E_NUM];                      // doubling-weighted counts

// ---------------- init: out = x (residual), zero accumulators ----------------
__global__ void init_kernel(const float* __restrict__ x, float* __restrict__ out) {
    int i = blockIdx.x * blockDim.x + threadIdx.x;
    if (i < (T_TOK * H_DIM) / 4) {
        ((float4*)out)[i] = ((const float4*)x)[i];
    }
    if (blockIdx.x == 0 && threadIdx.x < E_NUM) {
        g_cnt[threadIdx.x]  = 0;
        g_sumP[threadIdx.x] = 0.f;
        g_imp[threadIdx.x]  = 0.f;
        g_wc[threadIdx.x]   = 0.f;
    }
}

// ---------------- RMSNorm ----------------
__global__ void rmsnorm_kernel(const float* __restrict__ x, const float* __restrict__ ns) {
    int t = blockIdx.x, tid = threadIdx.x;            // 128 threads, 4 floats each
    float4 v = ((const float4*)(x + (size_t)t * H_DIM))[tid];
    float ss = v.x * v.x + v.y * v.y + v.z * v.z + v.w * v.w;
    #pragma unroll
    for (int o = 16; o; o >>= 1) ss += __shfl_xor_sync(0xffffffffu, ss, o);
    __shared__ float red[4];
    if ((tid & 31) == 0) red[tid >> 5] = ss;
    __syncthreads();
    float tot = red[0] + red[1] + red[2] + red[3];
    float r = rsqrtf(tot * (1.0f / H_DIM) + 1e-6f);
    float4 s = ((const float4*)ns)[tid];
    float4 o;
    o.x = v.x * r * s.x; o.y = v.y * r * s.y;
    o.z = v.z * r * s.z; o.w = v.w * r * s.w;
    ((float4*)(g_t + (size_t)t * H_DIM))[tid] = o;
}

// ---------------- gating: logits, softmax, top-4, routing lists, aux accumulators ----------------
__global__ void gate_kernel(const float* __restrict__ gw, const float* __restrict__ gb) {
    int t = blockIdx.x;
    int tid = threadIdx.x, w = tid >> 5, lane = tid & 31;   // 256 threads = 8 warps, warp w -> expert w
    __shared__ float sl[E_NUM];
    const float* tr = g_t + (size_t)t * H_DIM;
    float s = 0.f;
    for (int j = lane; j < H_DIM; j += 32) s += tr[j] * gw[w * H_DIM + j];
    #pragma unroll
    for (int o = 16; o; o >>= 1) s += __shfl_xor_sync(0xffffffffu, s, o);
    if (lane == 0) sl[w] = s + gb[w];
    __syncthreads();
    if (tid == 0) {
        float l[E_NUM], p[E_NUM];
        float m = -1e30f;
        #pragma unroll
        for (int e = 0; e < E_NUM; e++) { l[e] = sl[e]; m = fmaxf(m, l[e]); }
        float sum = 0.f;
        #pragma unroll
        for (int e = 0; e < E_NUM; e++) { p[e] = expf(l[e] - m); sum += p[e]; }
        float inv = 1.f / sum;
        #pragma unroll
        for (int e = 0; e < E_NUM; e++) {
            p[e] *= inv;
            atomicAdd(&g_sumP[e], p[e]);
            atomicAdd(&g_imp[e],  l[e]);
        }
        // top-4 (strict > keeps lowest index on ties, matching jax top_k)
        bool used[E_NUM] = {false,false,false,false,false,false,false,false};
        int   idx[KTOP];  float wv[KTOP];  float wsum = 0.f;
        #pragma unroll
        for (int k = 0; k < KTOP; k++) {
            int best = -1; float bv = -1.f;
            #pragma unroll
            for (int e = 0; e < E_NUM; e++)
                if (!used[e] && p[e] > bv) { bv = p[e]; best = e; }
            used[best] = true; idx[k] = best; wv[k] = bv; wsum += bv;
            atomicAdd(&g_wc[best], (float)(16 >> k));   // doubling = 2^(4-k)
        }
        float winv = 1.f / wsum;
        #pragma unroll
        for (int k = 0; k < KTOP; k++) {
            int e = idx[k];
            int slot = atomicAdd(&g_cnt[e], 1);
            g_tok[e * T_TOK + slot] = t;
            g_cw [e * T_TOK + slot] = wv[k] * winv;
        }
    }
}

// ---------------- GEMM1: h = t_gathered @ W1[e]^T (+b1), fused clip+SwiGLU -> g_a ----------------
// Tile: 64 rows x 128 cols, 256 threads (16x16), thread tile 4 rows x 8 cols (4 even/odd col pairs).
__global__ __launch_bounds__(256) void gemm1_kernel(const float* __restrict__ w1,
                                                    const float* __restrict__ b1) {
    int e = blockIdx.z;
    int nt = g_cnt[e];
    int row0 = blockIdx.x * 64;
    if (row0 >= nt) return;
    int colBase = blockIdx.y * 128;   // column in 2I space

    __shared__ float As[16][65];
    __shared__ float Bs[16][132];
    int tid = threadIdx.x, tx = tid & 15, ty = tid >> 4;
    const float* W = w1 + (size_t)e * (2 * I_DIM) * H_DIM;

    int tokA[4];
    #pragma unroll
    for (int j = 0; j < 4; j++) {
        int slot = row0 + ty + 16 * j;
        tokA[j] = g_tok[e * T_TOK + (slot < nt ? slot : nt - 1)];
    }

    float acc[4][8];
    #pragma unroll
    for (int i = 0; i < 4; i++)
        #pragma unroll
        for (int c = 0; c < 8; c++) acc[i][c] = 0.f;

    for (int k0 = 0; k0 < H_DIM; k0 += 16) {
        #pragma unroll
        for (int j = 0; j < 4; j++)
            As[tx][ty + 16 * j] = g_t[(size_t)tokA[j] * H_DIM + k0 + tx];
        #pragma unroll
        for (int j = 0; j < 8; j++)
            Bs[tx][ty + 16 * j] = W[(size_t)(colBase + ty + 16 * j) * H_DIM + k0 + tx];
        __syncthreads();
        #pragma unroll
        for (int k = 0; k < 16; k++) {
            float ra[4];
            #pragma unroll
            for (int i = 0; i < 4; i++) ra[i] = As[k][ty + 16 * i];
            float rb[8];
            #pragma unroll
            for (int g = 0; g < 4; g++) {
                rb[2 * g]     = Bs[k][32 * g + 2 * tx];
                rb[2 * g + 1] = Bs[k][32 * g + 2 * tx + 1];
            }
            #pragma unroll
            for (int i = 0; i < 4; i++)
                #pragma unroll
                for (int c = 0; c < 8; c++) acc[i][c] += ra[i] * rb[c];
        }
        __syncthreads();
    }

    const float* bias = b1 + (size_t)e * 2 * I_DIM;
    #pragma unroll
    for (int i = 0; i < 4; i++) {
        int slot = row0 + ty + 16 * i;
        if (slot >= nt) continue;
        float* arow = g_a + ((size_t)e * T_TOK + slot) * I_DIM + (colBase >> 1);
        #pragma unroll
        for (int g = 0; g < 4; g++) {
            int c = 32 * g + 2 * tx;
            float hg = acc[i][2 * g]     + bias[colBase + c];
            float hl = acc[i][2 * g + 1] + bias[colBase + c + 1];
            hg = fminf(fmaxf(hg, -7.f), 7.f);
            hl = fminf(fmaxf(hl, -7.f), 7.f);
            float sg = 1.f / (1.f + expf(-1.702f * hg));
            arow[16 * g + tx] = hg * sg + (hl + 1.f);
        }
    }
}

// ---------------- GEMM2: y = a @ W2[e]^T (+b2); out += coeff*y via atomics ----------------
__global__ __launch_bounds__(256) void gemm2_kernel(const float* __restrict__ w2,
                                                    const float* __restrict__ b2,
                                                    float* __restrict__ out) {
    int e = blockIdx.z;
    int nt = g_cnt[e];
    int row0 = blockIdx.x * 64;
    if (row0 >= nt) return;
    int colBase = blockIdx.y * 128;

    __shared__ float As[16][65];
    __shared__ float Bs[16][132];
    int tid = threadIdx.x, tx = tid & 15, ty = tid >> 4;
    const float* A = g_a + (size_t)e * T_TOK * I_DIM;
    const float* W = w2 + (size_t)e * H_DIM * I_DIM;

    int rowA[4];
    #pragma unroll
    for (int j = 0; j < 4; j++) {
        int slot = row0 + ty + 16 * j;
        rowA[j] = (slot < nt ? slot : nt - 1);
    }

    float acc[4][8];
    #pragma unroll
    for (int i = 0; i < 4; i++)
        #pragma unroll
        for (int c = 0; c < 8; c++) acc[i][c] = 0.f;

    for (int k0 = 0; k0 < I_DIM; k0 += 16) {
        #pragma unroll
        for (int j = 0; j < 4; j++)
            As[tx][ty + 16 * j] = A[(size_t)rowA[j] * I_DIM + k0 + tx];
        #pragma unroll
        for (int j = 0; j < 8; j++)
            Bs[tx][ty + 16 * j] = W[(size_t)(colBase + ty + 16 * j) * I_DIM + k0 + tx];
        __syncthreads();
        #pragma unroll
        for (int k = 0; k < 16; k++) {
            float ra[4];
            #pragma unroll
            for (int i = 0; i < 4; i++) ra[i] = As[k][ty + 16 * i];
            float rb[8];
            #pragma unroll
            for (int g = 0; g < 4; g++) {
                rb[2 * g]     = Bs[k][32 * g + 2 * tx];
                rb[2 * g + 1] = Bs[k][32 * g + 2 * tx + 1];
            }
            #pragma unroll
            for (int i = 0; i < 4; i++)
                #pragma unroll
                for (int c = 0; c < 8; c++) acc[i][c] += ra[i] * rb[c];
        }
        __syncthreads();
    }

    const float* bias = b2 + (size_t)e * H_DIM;
    #pragma unroll
    for (int i = 0; i < 4; i++) {
        int slot = row0 + ty + 16 * i;
        if (slot >= nt) continue;
        int token = g_tok[e * T_TOK + slot];
        float cw  = g_cw [e * T_TOK + slot];
        float* orow = out + (size_t)token * H_DIM;
        #pragma unroll
        for (int g = 0; g < 4; g++) {
            int c = colBase + 32 * g + 2 * tx;
            atomicAdd(&orow[c],     cw * (acc[i][2 * g]     + bias[c]));
            atomicAdd(&orow[c + 1], cw * (acc[i][2 * g + 1] + bias[c + 1]));
        }
    }
}

// ---------------- aux loss ----------------
__global__ void finalize_kernel(float* __restrict__ out, int out_size) {
    if (threadIdx.x == 0 && blockIdx.x == 0) {
        float load = 0.f;
        #pragma unroll
        for (int e = 0; e < E_NUM; e++) {
            float P = g_sumP[e] / (float)T_TOK;
            float D = g_wc[e] / (float)(T_TOK * KTOP);
            load += P * D;
        }
        load *= 0.01f * (float)E_NUM;           // W_LOAD * E
        float m = 0.f;
        #pragma unroll
        for (int e = 0; e < E_NUM; e++) m += g_imp[e];
        m *= (1.f / E_NUM);
        float v = 0.f;
        #pragma unroll
        for (int e = 0; e < E_NUM; e++) { float d = g_imp[e] - m; v += d * d; }
        v *= (1.f / (E_NUM - 1));               // ddof=1
        float cv = sqrtf(v) / (m + 1e-6f);
        out[out_size - 1] = 1.0f * (load + 0.01f * cv * cv);   // W_AUX*(load + W_IMP*cv^2)
    }
}

// ---------------- launch ----------------
extern "C" void kernel_launch(void* const* d_in, const int* in_sizes, int n_in,
                              void* d_out, int out_size) {
    const float* x  = (const float*)d_in[0];
    const float* ns = (const float*)d_in[1];
    const float* gw = (const float*)d_in[2];
    const float* gb = (const float*)d_in[3];
    const float* w1 = (const float*)d_in[4];
    const float* b1 = (const float*)d_in[5];
    const float* w2 = (const float*)d_in[6];
    const float* b2 = (const float*)d_in[7];
    float* out = (float*)d_out;

    init_kernel<<<(T_TOK * H_DIM / 4 + 255) / 256, 256>>>(x, out);
    rmsnorm_kernel<<<T_TOK, 128>>>(x, ns);
    gate_kernel<<<T_TOK, 256>>>(gw, gb);
    dim3 g1(T_TOK / 64, (2 * I_DIM) / 128, E_NUM);
    gemm1_kernel<<<g1, 256>>>(w1, b1);
    dim3 g2(T_TOK / 64, H_DIM / 128, E_NUM);
    gemm2_kernel<<<g2, 256>>>(w2, b2, out);
    finalize_kernel<<<1, 32>>>(out, out_size);
}

// round 4
// speedup vs baseline: 1.0038x; 1.0038x over previous
#include <cuda_runtime.h>
#include <math.h>

#define T_TOK 2048
#define H_DIM 512
#define I_DIM 512
#define E_NUM 8
#define KTOP  4

// ---------------- scratch (device globals, no allocs) ----------------
__device__ float g_t[T_TOK * H_DIM];                 // RMSNorm output
__device__ float g_a[(size_t)E_NUM * T_TOK * I_DIM]; // SwiGLU activations per expert slot
__device__ int   g_cnt[E_NUM];                       // tokens routed to each expert
__device__ int   g_tok[E_NUM * T_TOK];               // gathered token ids
__device__ float g_cw [E_NUM * T_TOK];               // combine coefficient per slot
__device__ float g_sumP[E_NUM];                      // sum of gate probs
__device__ float g_imp [E_NUM];                      // sum of gate logits (importance)
__device__ float g_wc  [E_NUM];                      // doubling-weighted counts

// ---------------- init: out = x (residual), zero accumulators ----------------
__global__ void init_kernel(const float* __restrict__ x, float* __restrict__ out) {
    int i = blockIdx.x * blockDim.x + threadIdx.x;
    if (i < (T_TOK * H_DIM) / 4) {
        ((float4*)out)[i] = ((const float4*)x)[i];
    }
    if (blockIdx.x == 0 && threadIdx.x < E_NUM) {
        g_cnt[threadIdx.x]  = 0;
        g_sumP[threadIdx.x] = 0.f;
        g_imp[threadIdx.x]  = 0.f;
        g_wc[threadIdx.x]   = 0.f;
    }
}

// ---------------- RMSNorm ----------------
__global__ void rmsnorm_kernel(const float* __restrict__ x, const float* __restrict__ ns) {
    int t = blockIdx.x, tid = threadIdx.x;            // 128 threads, 4 floats each
    float4 v = ((const float4*)(x + (size_t)t * H_DIM))[tid];
    float ss = v.x * v.x + v.y * v.y + v.z * v.z + v.w * v.w;
    #pragma unroll
    for (int o = 16; o; o >>= 1) ss += __shfl_xor_sync(0xffffffffu, ss, o);
    __shared__ float red[4];
    if ((tid & 31) == 0) red[tid >> 5] = ss;
    __syncthreads();
    float tot = red[0] + red[1] + red[2] + red[3];
    float r = rsqrtf(tot * (1.0f / H_DIM) + 1e-6f);
    float4 s = ((const float4*)ns)[tid];
    float4 o;
    o.x = v.x * r * s.x; o.y = v.y * r * s.y;
    o.z = v.z * r * s.z; o.w = v.w * r * s.w;
    ((float4*)(g_t + (size_t)t * H_DIM))[tid] = o;
}

// ---------------- gating: logits, softmax, top-4, routing lists, aux accumulators ----------------
__global__ void gate_kernel(const float* __restrict__ gw, const float* __restrict__ gb) {
    int t = blockIdx.x;
    int tid = threadIdx.x, w = tid >> 5, lane = tid & 31;   // 256 threads = 8 warps, warp w -> expert w
    __shared__ float sl[E_NUM];
    const float* tr = g_t + (size_t)t * H_DIM;
    float s = 0.f;
    for (int j = lane; j < H_DIM; j += 32) s += tr[j] * gw[w * H_DIM + j];
    #pragma unroll
    for (int o = 16; o; o >>= 1) s += __shfl_xor_sync(0xffffffffu, s, o);
    if (lane == 0) sl[w] = s + gb[w];
    __syncthreads();
    if (tid == 0) {
        float l[E_NUM], p[E_NUM];
        float m = -1e30f;
        #pragma unroll
        for (int e = 0; e < E_NUM; e++) { l[e] = sl[e]; m = fmaxf(m, l[e]); }
        float sum = 0.f;
        #pragma unroll
        for (int e = 0; e < E_NUM; e++) { p[e] = expf(l[e] - m); sum += p[e]; }
        float inv = 1.f / sum;
        #pragma unroll
        for (int e = 0; e < E_NUM; e++) {
            p[e] *= inv;
            atomicAdd(&g_sumP[e], p[e]);
            atomicAdd(&g_imp[e],  l[e]);
        }
        // top-4 (strict > keeps lowest index on ties, matching jax top_k)
        bool used[E_NUM] = {false,false,false,false,false,false,false,false};
        int   idx[KTOP];  float wv[KTOP];  float wsum = 0.f;
        #pragma unroll
        for (int k = 0; k < KTOP; k++) {
            int best = -1; float bv = -1.f;
            #pragma unroll
            for (int e = 0; e < E_NUM; e++)
                if (!used[e] && p[e] > bv) { bv = p[e]; best = e; }
            used[best] = true; idx[k] = best; wv[k] = bv; wsum += bv;
            atomicAdd(&g_wc[best], (float)(16 >> k));   // doubling = 2^(4-k)
        }
        float winv = 1.f / wsum;
        #pragma unroll
        for (int k = 0; k < KTOP; k++) {
            int e = idx[k];
            int slot = atomicAdd(&g_cnt[e], 1);
            g_tok[e * T_TOK + slot] = t;
            g_cw [e * T_TOK + slot] = wv[k] * winv;
        }
    }
}

// ---------------- GEMM1: h = t_gathered @ W1[e]^T (+b1), fused clip+SwiGLU -> g_a ----------------
// Tile: 64 rows x 128 cols, 256 threads (16x16), thread tile 4 rows x 8 cols (4 even/odd col pairs).
__global__ __launch_bounds__(256) void gemm1_kernel(const float* __restrict__ w1,
                                                    const float* __restrict__ b1) {
    int e = blockIdx.z;
    int nt = g_cnt[e];
    int row0 = blockIdx.x * 64;
    if (row0 >= nt) return;
    int colBase = blockIdx.y * 128;   // column in 2I space

    __shared__ float As[16][65];
    __shared__ float Bs[16][132];
    int tid = threadIdx.x, tx = tid & 15, ty = tid >> 4;
    const float* W = w1 + (size_t)e * (2 * I_DIM) * H_DIM;

    int tokA[4];
    #pragma unroll
    for (int j = 0; j < 4; j++) {
        int slot = row0 + ty + 16 * j;
        tokA[j] = g_tok[e * T_TOK + (slot < nt ? slot : nt - 1)];
    }

    float acc[4][8];
    #pragma unroll
    for (int i = 0; i < 4; i++)
        #pragma unroll
        for (int c = 0; c < 8; c++) acc[i][c] = 0.f;

    for (int k0 = 0; k0 < H_DIM; k0 += 16) {
        #pragma unroll
        for (int j = 0; j < 4; j++)
            As[tx][ty + 16 * j] = g_t[(size_t)tokA[j] * H_DIM + k0 + tx];
        #pragma unroll
        for (int j = 0; j < 8; j++)
            Bs[tx][ty + 16 * j] = W[(size_t)(colBase + ty + 16 * j) * H_DIM + k0 + tx];
        __syncthreads();
        #pragma unroll
        for (int k = 0; k < 16; k++) {
            float ra[4];
            #pragma unroll
            for (int i = 0; i < 4; i++) ra[i] = As[k][ty + 16 * i];
            float rb[8];
            #pragma unroll
            for (int g = 0; g < 4; g++) {
                rb[2 * g]     = Bs[k][32 * g + 2 * tx];
                rb[2 * g + 1] = Bs[k][32 * g + 2 * tx + 1];
            }
            #pragma unroll
            for (int i = 0; i < 4; i++)
                #pragma unroll
                for (int c = 0; c < 8; c++) acc[i][c] += ra[i] * rb[c];
        }
        __syncthreads();
    }

    const float* bias = b1 + (size_t)e * 2 * I_DIM;
    #pragma unroll
    for (int i = 0; i < 4; i++) {
        int slot = row0 + ty + 16 * i;
        if (slot >= nt) continue;
        float* arow = g_a + ((size_t)e * T_TOK + slot) * I_DIM + (colBase >> 1);
        #pragma unroll
        for (int g = 0; g < 4; g++) {
            int c = 32 * g + 2 * tx;
            float hg = acc[i][2 * g]     + bias[colBase + c];
            float hl = acc[i][2 * g + 1] + bias[colBase + c + 1];
            hg = fminf(fmaxf(hg, -7.f), 7.f);
            hl = fminf(fmaxf(hl, -7.f), 7.f);
            float sg = 1.f / (1.f + expf(-1.702f * hg));
            arow[16 * g + tx] = hg * sg + (hl + 1.f);
        }
    }
}

// ---------------- GEMM2: y = a @ W2[e]^T (+b2); out += coeff*y via atomics ----------------
__global__ __launch_bounds__(256) void gemm2_kernel(const float* __restrict__ w2,
                                                    const float* __restrict__ b2,
                                                    float* __restrict__ out) {
    int e = blockIdx.z;
    int nt = g_cnt[e];
    int row0 = blockIdx.x * 64;
    if (row0 >= nt) return;
    int colBase = blockIdx.y * 128;

    __shared__ float As[16][65];
    __shared__ float Bs[16][132];
    int tid = threadIdx.x, tx = tid & 15, ty = tid >> 4;
    const float* A = g_a + (size_t)e * T_TOK * I_DIM;
    const float* W = w2 + (size_t)e * H_DIM * I_DIM;

    int rowA[4];
    #pragma unroll
    for (int j = 0; j < 4; j++) {
        int slot = row0 + ty + 16 * j;
        rowA[j] = (slot < nt ? slot : nt - 1);
    }

    float acc[4][8];
    #pragma unroll
    for (int i = 0; i < 4; i++)
        #pragma unroll
        for (int c = 0; c < 8; c++) acc[i][c] = 0.f;

    for (int k0 = 0; k0 < I_DIM; k0 += 16) {
        #pragma unroll
        for (int j = 0; j < 4; j++)
            As[tx][ty + 16 * j] = A[(size_t)rowA[j] * I_DIM + k0 + tx];
        #pragma unroll
        for (int j = 0; j < 8; j++)
            Bs[tx][ty + 16 * j] = W[(size_t)(colBase + ty + 16 * j) * I_DIM + k0 + tx];
        __syncthreads();
        #pragma unroll
        for (int k = 0; k < 16; k++) {
            float ra[4];
            #pragma unroll
            for (int i = 0; i < 4; i++) ra[i] = As[k][ty + 16 * i];
            float rb[8];
            #pragma unroll
            for (int g = 0; g < 4; g++) {
                rb[2 * g]     = Bs[k][32 * g + 2 * tx];
                rb[2 * g + 1] = Bs[k][32 * g + 2 * tx + 1];
            }
            #pragma unroll
            for (int i = 0; i < 4; i++)
                #pragma unroll
                for (int c = 0; c < 8; c++) acc[i][c] += ra[i] * rb[c];
        }
        __syncthreads();
    }

    const float* bias = b2 + (size_t)e * H_DIM;
    #pragma unroll
    for (int i = 0; i < 4; i++) {
        int slot = row0 + ty + 16 * i;
        if (slot >= nt) continue;
        int token = g_tok[e * T_TOK + slot];
        float cw  = g_cw [e * T_TOK + slot];
        float* orow = out + (size_t)token * H_DIM;
        #pragma unroll
        for (int g = 0; g < 4; g++) {
            int c = colBase + 32 * g + 2 * tx;
            atomicAdd(&orow[c],     cw * (acc[i][2 * g]     + bias[c]));
            atomicAdd(&orow[c + 1], cw * (acc[i][2 * g + 1] + bias[c + 1]));
        }
    }
}

// ---------------- aux loss ----------------
__global__ void finalize_kernel(float* __restrict__ out, int out_size) {
    if (threadIdx.x == 0 && blockIdx.x == 0) {
        float load = 0.f;
        #pragma unroll
        for (int e = 0; e < E_NUM; e++) {
            float P = g_sumP[e] / (float)T_TOK;
            float D = g_wc[e] / (float)(T_TOK * KTOP);
            load += P * D;
        }
        load *= 0.01f * (float)E_NUM;           // W_LOAD * E
        float m = 0.f;
        #pragma unroll
        for (int e = 0; e < E_NUM; e++) m += g_imp[e];
        m *= (1.f / E_NUM);
        float v = 0.f;
        #pragma unroll
        for (int e = 0; e < E_NUM; e++) { float d = g_imp[e] - m; v += d * d; }
        v *= (1.f / (E_NUM - 1));               // ddof=1
        float cv = sqrtf(v) / (m + 1e-6f);
        out[out_size - 1] = 1.0f * (load + 0.01f * cv * cv);   // W_AUX*(load + W_IMP*cv^2)
    }
}

// ---------------- launch ----------------
extern "C" void kernel_launch(void* const* d_in, const int* in_sizes, int n_in,
                              void* d_out, int out_size) {
    const float* x  = (const float*)d_in[0];
    const float* ns = (const float*)d_in[1];
    const float* gw = (const float*)d_in[2];
    const float* gb = (const float*)d_in[3];
    const float* w1 = (const float*)d_in[4];
    const float* b1 = (const float*)d_in[5];
    const float* w2 = (const float*)d_in[6];
    const float* b2 = (const float*)d_in[7];
    float* out = (float*)d_out;

    init_kernel<<<(T_TOK * H_DIM / 4 + 255) / 256, 256>>>(x, out);
    rmsnorm_kernel<<<T_TOK, 128>>>(x, ns);
    gate_kernel<<<T_TOK, 256>>>(gw, gb);
    dim3 g1(T_TOK / 64, (2 * I_DIM) / 128, E_NUM);
    gemm1_kernel<<<g1, 256>>>(w1, b1);
    dim3 g2(T_TOK / 64, H_DIM / 128, E_NUM);
    gemm2_kernel<<<g2, 256>>>(w2, b2, out);
    finalize_kernel<<<1, 32>>>(out, out_size);
}

// round 5
// speedup vs baseline: 1.0056x; 1.0018x over previous
#include <cuda_runtime.h>
#include <math.h>

#define T_TOK 2048
#define H_DIM 512
#define I_DIM 512
#define E_NUM 8
#define KTOP  4

// ---------------- scratch (device globals, no allocs) ----------------
__device__ float g_t[T_TOK * H_DIM];                 // RMSNorm output
__device__ float g_a[(size_t)E_NUM * T_TOK * I_DIM]; // SwiGLU activations per expert slot
__device__ int   g_cnt[E_NUM];                       // tokens routed to each expert
__device__ int   g_tok[E_NUM * T_TOK];               // gathered token ids
__device__ float g_cw [E_NUM * T_TOK];               // combine coefficient per slot
__device__ float g_sumP[E_NUM];                      // sum of gate probs
__device__ float g_imp [E_NUM];                      // sum of gate logits (importance)
__device__ float g_wc  [E_NUM];                      // doubling-weighted counts

// ---------------- init: out = x (residual), zero accumulators ----------------
__global__ void init_kernel(const float* __restrict__ x, float* __restrict__ out) {
    int i = blockIdx.x * blockDim.x + threadIdx.x;
    if (i < (T_TOK * H_DIM) / 4) {
        ((float4*)out)[i] = ((const float4*)x)[i];
    }
    if (blockIdx.x == 0 && threadIdx.x < E_NUM) {
        g_cnt[threadIdx.x]  = 0;
        g_sumP[threadIdx.x] = 0.f;
        g_imp[threadIdx.x]  = 0.f;
        g_wc[threadIdx.x]   = 0.f;
    }
}

// ---------------- RMSNorm ----------------
__global__ void rmsnorm_kernel(const float* __restrict__ x, const float* __restrict__ ns) {
    int t = blockIdx.x, tid = threadIdx.x;            // 128 threads, 4 floats each
    float4 v = ((const float4*)(x + (size_t)t * H_DIM))[tid];
    float ss = v.x * v.x + v.y * v.y + v.z * v.z + v.w * v.w;
    #pragma unroll
    for (int o = 16; o; o >>= 1) ss += __shfl_xor_sync(0xffffffffu, ss, o);
    __shared__ float red[4];
    if ((tid & 31) == 0) red[tid >> 5] = ss;
    __syncthreads();
    float tot = red[0] + red[1] + red[2] + red[3];
    float r = rsqrtf(tot * (1.0f / H_DIM) + 1e-6f);
    float4 s = ((const float4*)ns)[tid];
    float4 o;
    o.x = v.x * r * s.x; o.y = v.y * r * s.y;
    o.z = v.z * r * s.z; o.w = v.w * r * s.w;
    ((float4*)(g_t + (size_t)t * H_DIM))[tid] = o;
}

// ---------------- gating: logits, softmax, top-4, routing lists, aux accumulators ----------------
__global__ void gate_kernel(const float* __restrict__ gw, const float* __restrict__ gb) {
    int t = blockIdx.x;
    int tid = threadIdx.x, w = tid >> 5, lane = tid & 31;   // 256 threads = 8 warps, warp w -> expert w
    __shared__ float sl[E_NUM];
    const float* tr = g_t + (size_t)t * H_DIM;
    float s = 0.f;
    for (int j = lane; j < H_DIM; j += 32) s += tr[j] * gw[w * H_DIM + j];
    #pragma unroll
    for (int o = 16; o; o >>= 1) s += __shfl_xor_sync(0xffffffffu, s, o);
    if (lane == 0) sl[w] = s + gb[w];
    __syncthreads();
    if (tid == 0) {
        float l[E_NUM], p[E_NUM];
        float m = -1e30f;
        #pragma unroll
        for (int e = 0; e < E_NUM; e++) { l[e] = sl[e]; m = fmaxf(m, l[e]); }
        float sum = 0.f;
        #pragma unroll
        for (int e = 0; e < E_NUM; e++) { p[e] = expf(l[e] - m); sum += p[e]; }
        float inv = 1.f / sum;
        #pragma unroll
        for (int e = 0; e < E_NUM; e++) {
            p[e] *= inv;
            atomicAdd(&g_sumP[e], p[e]);
            atomicAdd(&g_imp[e],  l[e]);
        }
        // top-4 (strict > keeps lowest index on ties, matching jax top_k)
        bool used[E_NUM] = {false,false,false,false,false,false,false,false};
        int   idx[KTOP];  float wv[KTOP];  float wsum = 0.f;
        #pragma unroll
        for (int k = 0; k < KTOP; k++) {
            int best = -1; float bv = -1.f;
            #pragma unroll
            for (int e = 0; e < E_NUM; e++)
                if (!used[e] && p[e] > bv) { bv = p[e]; best = e; }
            used[best] = true; idx[k] = best; wv[k] = bv; wsum += bv;
            atomicAdd(&g_wc[best], (float)(16 >> k));   // doubling = 2^(4-k)
        }
        float winv = 1.f / wsum;
        #pragma unroll
        for (int k = 0; k < KTOP; k++) {
            int e = idx[k];
            int slot = atomicAdd(&g_cnt[e], 1);
            g_tok[e * T_TOK + slot] = t;
            g_cw [e * T_TOK + slot] = wv[k] * winv;
        }
    }
}

// ---------------- GEMM1: h = t_gathered @ W1[e]^T (+b1), fused clip+SwiGLU -> g_a ----------------
// Tile: 64 rows x 128 cols, 256 threads (16x16), thread tile 4 rows x 8 cols (4 even/odd col pairs).
__global__ __launch_bounds__(256) void gemm1_kernel(const float* __restrict__ w1,
                                                    const float* __restrict__ b1) {
    int e = blockIdx.z;
    int nt = g_cnt[e];
    int row0 = blockIdx.x * 64;
    if (row0 >= nt) return;
    int colBase = blockIdx.y * 128;   // column in 2I space

    __shared__ float As[16][65];
    __shared__ float Bs[16][132];
    int tid = threadIdx.x, tx = tid & 15, ty = tid >> 4;
    const float* W = w1 + (size_t)e * (2 * I_DIM) * H_DIM;

    int tokA[4];
    #pragma unroll
    for (int j = 0; j < 4; j++) {
        int slot = row0 + ty + 16 * j;
        tokA[j] = g_tok[e * T_TOK + (slot < nt ? slot : nt - 1)];
    }

    float acc[4][8];
    #pragma unroll
    for (int i = 0; i < 4; i++)
        #pragma unroll
        for (int c = 0; c < 8; c++) acc[i][c] = 0.f;

    for (int k0 = 0; k0 < H_DIM; k0 += 16) {
        #pragma unroll
        for (int j = 0; j < 4; j++)
            As[tx][ty + 16 * j] = g_t[(size_t)tokA[j] * H_DIM + k0 + tx];
        #pragma unroll
        for (int j = 0; j < 8; j++)
            Bs[tx][ty + 16 * j] = W[(size_t)(colBase + ty + 16 * j) * H_DIM + k0 + tx];
        __syncthreads();
        #pragma unroll
        for (int k = 0; k < 16; k++) {
            float ra[4];
            #pragma unroll
            for (int i = 0; i < 4; i++) ra[i] = As[k][ty + 16 * i];
            float rb[8];
            #pragma unroll
            for (int g = 0; g < 4; g++) {
                rb[2 * g]     = Bs[k][32 * g + 2 * tx];
                rb[2 * g + 1] = Bs[k][32 * g + 2 * tx + 1];
            }
            #pragma unroll
            for (int i = 0; i < 4; i++)
                #pragma unroll
                for (int c = 0; c < 8; c++) acc[i][c] += ra[i] * rb[c];
        }
        __syncthreads();
    }

    const float* bias = b1 + (size_t)e * 2 * I_DIM;
    #pragma unroll
    for (int i = 0; i < 4; i++) {
        int slot = row0 + ty + 16 * i;
        if (slot >= nt) continue;
        float* arow = g_a + ((size_t)e * T_TOK + slot) * I_DIM + (colBase >> 1);
        #pragma unroll
        for (int g = 0; g < 4; g++) {
            int c = 32 * g + 2 * tx;
            float hg = acc[i][2 * g]     + bias[colBase + c];
            float hl = acc[i][2 * g + 1] + bias[colBase + c + 1];
            hg = fminf(fmaxf(hg, -7.f), 7.f);
            hl = fminf(fmaxf(hl, -7.f), 7.f);
            float sg = 1.f / (1.f + expf(-1.702f * hg));
            arow[16 * g + tx] = hg * sg + (hl + 1.f);
        }
    }
}

// ---------------- GEMM2: y = a @ W2[e]^T (+b2); out += coeff*y via atomics ----------------
__global__ __launch_bounds__(256) void gemm2_kernel(const float* __restrict__ w2,
                                                    const float* __restrict__ b2,
                                                    float* __restrict__ out) {
    int e = blockIdx.z;
    int nt = g_cnt[e];
    int row0 = blockIdx.x * 64;
    if (row0 >= nt) return;
    int colBase = blockIdx.y * 128;

    __shared__ float As[16][65];
    __shared__ float Bs[16][132];
    int tid = threadIdx.x, tx = tid & 15, ty = tid >> 4;
    const float* A = g_a + (size_t)e * T_TOK * I_DIM;
    const float* W = w2 + (size_t)e * H_DIM * I_DIM;

    int rowA[4];
    #pragma unroll
    for (int j = 0; j < 4; j++) {
        int slot = row0 + ty + 16 * j;
        rowA[j] = (slot < nt ? slot : nt - 1);
    }

    float acc[4][8];
    #pragma unroll
    for (int i = 0; i < 4; i++)
        #pragma unroll
        for (int c = 0; c < 8; c++) acc[i][c] = 0.f;

    for (int k0 = 0; k0 < I_DIM; k0 += 16) {
        #pragma unroll
        for (int j = 0; j < 4; j++)
            As[tx][ty + 16 * j] = A[(size_t)rowA[j] * I_DIM + k0 + tx];
        #pragma unroll
        for (int j = 0; j < 8; j++)
            Bs[tx][ty + 16 * j] = W[(size_t)(colBase + ty + 16 * j) * I_DIM + k0 + tx];
        __syncthreads();
        #pragma unroll
        for (int k = 0; k < 16; k++) {
            float ra[4];
            #pragma unroll
            for (int i = 0; i < 4; i++) ra[i] = As[k][ty + 16 * i];
            float rb[8];
            #pragma unroll
            for (int g = 0; g < 4; g++) {
                rb[2 * g]     = Bs[k][32 * g + 2 * tx];
                rb[2 * g + 1] = Bs[k][32 * g + 2 * tx + 1];
            }
            #pragma unroll
            for (int i = 0; i < 4; i++)
                #pragma unroll
                for (int c = 0; c < 8; c++) acc[i][c] += ra[i] * rb[c];
        }
        __syncthreads();
    }

    const float* bias = b2 + (size_t)e * H_DIM;
    #pragma unroll
    for (int i = 0; i < 4; i++) {
        int slot = row0 + ty + 16 * i;
        if (slot >= nt) continue;
        int token = g_tok[e * T_TOK + slot];
        float cw  = g_cw [e * T_TOK + slot];
        float* orow = out + (size_t)token * H_DIM;
        #pragma unroll
        for (int g = 0; g < 4; g++) {
            int c = colBase + 32 * g + 2 * tx;
            atomicAdd(&orow[c],     cw * (acc[i][2 * g]     + bias[c]));
            atomicAdd(&orow[c + 1], cw * (acc[i][2 * g + 1] + bias[c + 1]));
        }
    }
}

// ---------------- aux loss ----------------
__global__ void finalize_kernel(float* __restrict__ out, int out_size) {
    if (threadIdx.x == 0 && blockIdx.x == 0) {
        float load = 0.f;
        #pragma unroll
        for (int e = 0; e < E_NUM; e++) {
            float P = g_sumP[e] / (float)T_TOK;
            float D = g_wc[e] / (float)(T_TOK * KTOP);
            load += P * D;
        }
        load *= 0.01f * (float)E_NUM;           // W_LOAD * E
        float m = 0.f;
        #pragma unroll
        for (int e = 0; e < E_NUM; e++) m += g_imp[e];
        m *= (1.f / E_NUM);
        float v = 0.f;
        #pragma unroll
        for (int e = 0; e < E_NUM; e++) { float d = g_imp[e] - m; v += d * d; }
        v *= (1.f / (E_NUM - 1));               // ddof=1
        float cv = sqrtf(v) / (m + 1e-6f);
        out[out_size - 1] = 1.0f * (load + 0.01f * cv * cv);   // W_AUX*(load + W_IMP*cv^2)
    }
}

// ---------------- launch ----------------
extern "C" void kernel_launch(void* const* d_in, const int* in_sizes, int n_in,
                              void* d_out, int out_size) {
    const float* x  = (const float*)d_in[0];
    const float* ns = (const float*)d_in[1];
    const float* gw = (const float*)d_in[2];
    const float* gb = (const float*)d_in[3];
    const float* w1 = (const float*)d_in[4];
    const float* b1 = (const float*)d_in[5];
    const float* w2 = (const float*)d_in[6];
    const float* b2 = (const float*)d_in[7];
    float* out = (float*)d_out;

    init_kernel<<<(T_TOK * H_DIM / 4 + 255) / 256, 256>>>(x, out);
    rmsnorm_kernel<<<T_TOK, 128>>>(x, ns);
    gate_kernel<<<T_TOK, 256>>>(gw, gb);
    dim3 g1(T_TOK / 64, (2 * I_DIM) / 128, E_NUM);
    gemm1_kernel<<<g1, 256>>>(w1, b1);
    dim3 g2(T_TOK / 64, H_DIM / 128, E_NUM);
    gemm2_kernel<<<g2, 256>>>(w2, b2, out);
    finalize_kernel<<<1, 32>>>(out, out_size);
}